// round 16
// baseline (speedup 1.0000x reference)
#include <cuda_runtime.h>

// DTWLoss B=64, T=1024. Warp-pipelined column-sweep DP with fused path loss.
// ONE CTA per batch: 16 warps x 32 lanes x 2 rows each = 1024 rows, 512 thr.
// 16-stage pipeline, CW=32, skew-1 blocking rendezvous named barriers
// (ids 1..15), no cross-CTA junction. 4 warps/SMSP hide SHFL/LDS latency.
// Per-cell math identical to R14 (FMNMX c-chain, R8 L tie-breaks).

#define Tn 1024
#define Bn 64
#define CW 32
#define NWARP 16
#define NTH 512
#define INFV 1e30f

__device__ float    g_losses[Bn];
__device__ unsigned g_count;     // zero-init; last CTA resets each launch

__device__ __forceinline__ float fsqrt_ap(float x) {
    float r;
    asm("sqrt.approx.f32 %0, %1;" : "=f"(r) : "f"(x));
    return r;
}
#define BARSYNC(id) asm volatile("bar.sync %0, 64;" :: "r"(id) : "memory")

// One 32(or 31)-step chunk: 2 rows per lane (R14 body, bit-identical math).
template<int NSTEPS>
__device__ __forceinline__ void run_chunk(
    int s0, bool is_lane0, bool is_lane31,
    const float2* __restrict__ bp, const float2* __restrict__ qp,
    float2* outp, int msk, float2* sinkp,
    float px0, float py0, float px1, float py1, float sc0, float sc1,
    float& c0, float& c1, float& L0, float& L1,
    float& upc, float& upL, float& p_uc, float& p_uL)
{
#pragma unroll 4
    for (int k = 0; k < NSTEPS; ++k) {
        float2 bv = bp[k];                     // uniform broadcast LDS
        const float uc = is_lane0 ? bv.x : upc;
        const float uL = is_lane0 ? bv.y : upL;
        float2 q = qp[k];

        // distances + path-cost terms for both rows (independent, ILP)
        const float dx0 = px0 - q.x, dy0 = py0 - q.y;
        const float dx1 = px1 - q.x, dy1 = py1 - q.y;
        const float d0 = fsqrt_ap(fmaf(dx0, dx0, dy0 * dy0));
        const float d1 = fsqrt_ap(fmaf(dx1, dx1, dy1 * dy1));
        const float e0 = fmaf(fabsf(dx0), sc0, fabsf(dy0) * sc1);
        const float e1 = fmaf(fabsf(dx1), sc0, fabsf(dy1) * sc1);

        const float lc0 = c0, lL0 = L0, lc1 = c1, lL1 = L1;
        // row 0: diag=p_uc, up=uc, left=lc0. FMNMX chain; tie order diag,up,left.
        const float mul0 = fminf(uc, lc0);
        const bool  pu0  = (uc <= lc0);
        const float Lv0  = pu0 ? uL : lL0;
        const bool  pd0  = (p_uc <= mul0);
        c0 = d0 + fminf(p_uc, mul0);
        L0 = e0 + (pd0 ? p_uL : Lv0);
        // row 1: diag=lc0(old), up=c0(new), left=lc1
        const float mul1 = fminf(c0, lc1);
        const bool  pu1  = (c0 <= lc1);
        const float Lv1  = pu1 ? L0 : lL1;
        const bool  pd1  = (lc0 <= mul1);
        c1 = d1 + fminf(lc0, mul1);
        L1 = e1 + (pd1 ? lL0 : Lv1);

        p_uc = uc; p_uL = uL;

        // branch-free boundary store (lane31 -> real target, others -> sink)
        const int j = s0 + k - 31;
        float2* sta = is_lane31 ? (outp + (j & msk)) : sinkp;   // STS.64
        *sta = make_float2(c1, L1);

        // pipelined lane handoff for next step
        upc = __shfl_up_sync(0xffffffffu, c1, 1);
        upL = __shfl_up_sync(0xffffffffu, L1, 1);
    }
}

__global__ void __launch_bounds__(NTH, 1)
dtw_kernel(const float* __restrict__ preds,
           const float* __restrict__ targs,
           const float* __restrict__ subcoef,
           float* __restrict__ out)
{
    __shared__ float2 sq_full[32 + Tn + 64];   // padded target coords
    __shared__ float2 bnd[NWARP - 1][128];     // 4-deep chunk rings (warp w -> w+1)
    __shared__ float2 sINF[128];               // INF boundary (warp 0)
    __shared__ float2 sink15[32];              // warp15 boundary dump ring
    __shared__ float2 scratch[NTH];            // smem store sink

    const int b    = blockIdx.x;
    const int t    = threadIdx.x;
    const int lane = t & 31;
    const int warp = t >> 5;
    const int rowbase = warp * 64 + lane * 2;  // 16*64 = 1024 rows total

    // ---- stage inputs ----
    const float* tb = targs + (size_t)b * Tn * 4;
    for (int j = t; j < Tn; j += NTH) {
        float4 v = *(const float4*)(tb + j * 4);
        sq_full[32 + j] = make_float2(v.x, v.y);
    }
    if (t < 32)  sq_full[t] = make_float2(0.f, 0.f);
    if (t < 64)  sq_full[32 + Tn + t] = make_float2(0.f, 0.f);
    if (t < 128) sINF[t] = make_float2(INFV, 0.f);

    const float* pb = preds + (size_t)b * Tn * 4;
    float4 p0 = *(const float4*)(pb + (size_t)rowbase * 4);
    float4 p1 = *(const float4*)(pb + (size_t)(rowbase + 1) * 4);
    const float px0 = p0.x, py0 = p0.y, px1 = p1.x, py1 = p1.y;
    const float sc0 = subcoef[0];
    const float sc1 = subcoef[1];

    float c0 = INFV, c1 = INFV, L0 = 0.f, L1 = 0.f;
    if (t == 0) c0 = 0.f;              // virtual C(0,-1)=0 -> C(0,0)=D(0,0)
    float upc = INFV, upL = 0.f;       // pipelined shfl result
    float p_uc = INFV, p_uL = 0.f;     // previous step's up = diag source

    const bool is_lane0  = (lane == 0);
    const bool is_lane31 = (lane == 31);

    // lane0 boundary-read source; lane31 boundary-write target
    const float2* bsrc = (warp == 0) ? sINF : bnd[warp - 1];
    float2* outp;
    int msk;
    if (warp < NWARP - 1) { outp = bnd[warp]; msk = 127; }
    else                  { outp = sink15;    msk = 31;  }
    float2* sinkp = &scratch[t];

    __syncthreads();

    for (int cc = 0; cc <= 32; ++cc) {
        const int s0 = cc * CW;
        // ---- prologue: consumer waits for producer (warp-1) chunk cc+1 done ----
        if (cc < 32 && warp > 0) BARSYNC(warp);

        const float2* bp = bsrc + ((cc & 3) << 5);
        const float2* qp = sq_full + 32 + s0 - lane;

        if (cc < 32) run_chunk<32>(s0, is_lane0, is_lane31, bp, qp, outp, msk, sinkp,
                                   px0, py0, px1, py1, sc0, sc1,
                                   c0, c1, L0, L1, upc, upL, p_uc, p_uL);
        else         run_chunk<31>(s0, is_lane0, is_lane31, bp, qp, outp, msk, sinkp,
                                   px0, py0, px1, py1, sc0, sc1,
                                   c0, c1, L0, L1, upc, upL, p_uc, p_uL);

        // ---- epilogue: producer release (chunk cc done -> consumer runs cc-1) ----
        if (cc >= 1 && warp < NWARP - 1) BARSYNC(warp + 1);
    }

    // ---- fused reduction across the 64 CTAs ----
    if (t == NTH - 1) {
        g_losses[b] = L1;              // row 1023, col 1023
        __threadfence();
        unsigned old = atomicAdd(&g_count, 1u);
        if (old == Bn - 1) {
            __threadfence();
            float s = 0.f;
            const volatile float* gl = g_losses;
#pragma unroll 8
            for (int i = 0; i < Bn; ++i) s += gl[i];
            out[0] = s;
            g_count = 0;               // reset for next graph replay
        }
    }
}

extern "C" void kernel_launch(void* const* d_in, const int* in_sizes, int n_in,
                              void* d_out, int out_size)
{
    const float* preds   = (const float*)d_in[0];
    const float* targs   = (const float*)d_in[1];
    const float* subcoef = (const float*)d_in[2];
    float* out = (float*)d_out;

    dtw_kernel<<<Bn, NTH>>>(preds, targs, subcoef, out);
}